// round 14
// baseline (speedup 1.0000x reference)
#include <cuda_runtime.h>
#include <cuda_bf16.h>
#include <cstdint>

#define BATCH  2
#define CH     512
#define NTOKB  4096              // tokens per batch (H*W)
#define NTOK   (BATCH * NTOKB)   // 8192
#define NGROUP 32
#define CPG    (CH / NGROUP)     // 16
#define EPS    1e-5f
#define SCALE  0.04419417382415922f   // 1/sqrt(512)

// ---------------- scratch (device globals; no allocations allowed) ----------
__device__ float g_t[(size_t)NTOK * CH];                 // normalized tokens [B*N, C]
__device__ float g_q[(size_t)NTOK * CH];
__device__ float g_k[(size_t)NTOK * CH];
__device__ float g_v[(size_t)NTOK * CH];
__device__ float g_o[(size_t)NTOK * CH];
__device__ __nv_bfloat16 g_sh[(size_t)BATCH * NTOKB * NTOKB];  // exp(scores), bf16, 64 MB
__device__ __nv_bfloat16 g_vt[(size_t)BATCH * CH * NTOKB];     // V^T bf16 [B][C][N]
__device__ float g_rowsum[NTOK];                          // softmax denominators

// ---------------- primitives ------------------------------------------------
__device__ __forceinline__ void mma_tf32(float* d, const unsigned* a, const unsigned* b) {
    asm volatile(
        "mma.sync.aligned.m16n8k8.row.col.f32.tf32.tf32.f32 "
        "{%0,%1,%2,%3}, {%4,%5,%6,%7}, {%8,%9}, {%0,%1,%2,%3};\n"
        : "+f"(d[0]), "+f"(d[1]), "+f"(d[2]), "+f"(d[3])
        : "r"(a[0]), "r"(a[1]), "r"(a[2]), "r"(a[3]), "r"(b[0]), "r"(b[1]));
}
__device__ __forceinline__ void mma_bf16(float* d, const unsigned* a, const unsigned* b) {
    asm volatile(
        "mma.sync.aligned.m16n8k16.row.col.f32.bf16.bf16.f32 "
        "{%0,%1,%2,%3}, {%4,%5,%6,%7}, {%8,%9}, {%0,%1,%2,%3};\n"
        : "+f"(d[0]), "+f"(d[1]), "+f"(d[2]), "+f"(d[3])
        : "r"(a[0]), "r"(a[1]), "r"(a[2]), "r"(a[3]), "r"(b[0]), "r"(b[1]));
}

__device__ __forceinline__ unsigned smem_u32(const void* p) {
    return (unsigned)__cvta_generic_to_shared(p);
}
#define CP16(dst, src) asm volatile("cp.async.cg.shared.global [%0], [%1], 16;" :: "r"(dst), "l"(src))
#define CPCOMMIT()     asm volatile("cp.async.commit_group;")
#define CPWAIT1()      asm volatile("cp.async.wait_group 1;")

// ============================================================================
// Unified big-tile mainloop: block 128x256, 256 thr = 8 warps (2m x 4n),
// warp tile 64x64 -> 4x8 fragments.  k-chunk = 64 bytes per row
// (16 fp32 for tf32 / 32 bf16 for bf16) -> 2 mma k-steps per chunk.
// pitch 20 b32, conflict-free fragment LDS; ~1.0 LDS.32 per mma.
// ============================================================================
#define P2 20
struct SM2 { unsigned A[3][128][P2]; unsigned B[3][256][P2]; };   // 92,160 B

__device__ __forceinline__ void load2_A(unsigned (*dst)[P2], const char* src,
                                        size_t ld, int tid) {
#pragma unroll
    for (int i = 0; i < 2; i++) {
        int c = i * 256 + tid;
        int r = c >> 2, s = c & 3;
        CP16(smem_u32(&dst[r][s * 4]), src + (size_t)r * ld + s * 16);
    }
}
__device__ __forceinline__ void load2_B(unsigned (*dst)[P2], const char* src,
                                        size_t ld, int tid) {
#pragma unroll
    for (int i = 0; i < 4; i++) {
        int c = i * 256 + tid;
        int r = c >> 2, s = c & 3;
        CP16(smem_u32(&dst[r][s * 4]), src + (size_t)r * ld + s * 16);
    }
}

template<bool BF16>
__device__ __forceinline__ void main2(const char* Ag, const char* Bg,
                                      size_t lda, size_t ldb, int NK,
                                      SM2* sm, float acc[4][8][4])
{
    const int tid = threadIdx.x;
    const int lane = tid & 31, w = tid >> 5;
    const int wm0 = (w >> 2) * 64, wn0 = (w & 3) * 64;
    const int fg = lane >> 2, fq = lane & 3;

    load2_A(sm->A[0], Ag, lda, tid);
    load2_B(sm->B[0], Bg, ldb, tid);
    CPCOMMIT();
    load2_A(sm->A[1], Ag + 64, lda, tid);
    load2_B(sm->B[1], Bg + 64, ldb, tid);
    CPCOMMIT();

    int cur = 0, nxt = 2;
    for (int it = 0; it < NK; ++it) {
        CPWAIT1();
        __syncthreads();
        if (it + 2 < NK) {
            load2_A(sm->A[nxt], Ag + (size_t)(it + 2) * 64, lda, tid);
            load2_B(sm->B[nxt], Bg + (size_t)(it + 2) * 64, ldb, tid);
        }
        CPCOMMIT();

        const unsigned (*As)[P2] = sm->A[cur];
        const unsigned (*Bs)[P2] = sm->B[cur];
#pragma unroll
        for (int ks = 0; ks < 2; ks++) {
            const int c0 = ks * 8 + fq;           // b32 column of first frag reg
            unsigned bf[8][2];
#pragma unroll
            for (int nt = 0; nt < 8; nt++) {
                const int bn = wn0 + nt * 8 + fg;
                bf[nt][0] = Bs[bn][c0];
                bf[nt][1] = Bs[bn][c0 + 4];
            }
#pragma unroll
            for (int mt = 0; mt < 4; mt++) {
                unsigned af[4];
                const int am = wm0 + mt * 16 + fg;
                af[0] = As[am][c0];     af[1] = As[am + 8][c0];
                af[2] = As[am][c0 + 4]; af[3] = As[am + 8][c0 + 4];
#pragma unroll
                for (int nt = 0; nt < 8; nt++) {
                    if (BF16) mma_bf16(acc[mt][nt], af, bf[nt]);
                    else      mma_tf32(acc[mt][nt], af, bf[nt]);
                }
            }
        }
        cur = (cur == 2) ? 0 : cur + 1;
        nxt = (nxt == 2) ? 0 : nxt + 1;
    }
}

// ---------------- fused Q/K/V projection (tf32, big tile) -------------------
__global__ __launch_bounds__(256) void gemm_qkv(
    const float* __restrict__ t,
    const float* __restrict__ wq, const float* __restrict__ bq, float* __restrict__ q,
    const float* __restrict__ wk, const float* __restrict__ bk, float* __restrict__ k,
    const float* __restrict__ wv, const float* __restrict__ bv, float* __restrict__ v)
{
    extern __shared__ char dynsm[];
    SM2* sm = (SM2*)dynsm;
    const float* W  = blockIdx.z == 0 ? wq : blockIdx.z == 1 ? wk : wv;
    const float* bs = blockIdx.z == 0 ? bq : blockIdx.z == 1 ? bk : bv;
    float*       C  = blockIdx.z == 0 ? q  : blockIdx.z == 1 ? k  : v;
    const int m0 = blockIdx.y * 128, n0 = blockIdx.x * 256;

    float acc[4][8][4] = {};
    main2<false>((const char*)(t + (size_t)m0 * CH), (const char*)(W + (size_t)n0 * CH),
                 (size_t)CH * 4, (size_t)CH * 4, (CH * 4) / 64, sm, acc);

    const int tid = threadIdx.x, lane = tid & 31, w = tid >> 5;
    const int wm0 = (w >> 2) * 64, wn0 = (w & 3) * 64;
    const int fg = lane >> 2, fq = lane & 3;
#pragma unroll
    for (int nt = 0; nt < 8; nt++) {
        const int col = n0 + wn0 + nt * 8 + 2 * fq;
        const float b0 = bs[col];
        const float b1 = bs[col + 1];
#pragma unroll
        for (int mt = 0; mt < 4; mt++) {
            const int row = m0 + wm0 + mt * 16 + fg;
            float2 v0 = { acc[mt][nt][0] + b0, acc[mt][nt][1] + b1 };
            float2 v1 = { acc[mt][nt][2] + b0, acc[mt][nt][3] + b1 };
            *(float2*)&C[(size_t)row * CH + col]       = v0;
            *(float2*)&C[(size_t)(row + 8) * CH + col] = v1;
        }
    }
}

// ---------------- S-gemm: S = exp(scale * Q K^T) -> bf16 + rowsum -----------
__global__ __launch_bounds__(256) void gemm_s(
    const float* __restrict__ q, const float* __restrict__ k)
{
    extern __shared__ char dynsm[];
    SM2* sm = (SM2*)dynsm;
    const int m0 = blockIdx.y * 128, n0 = blockIdx.x * 256, z = blockIdx.z;
    const char* Ag = (const char*)(q + (size_t)(z * NTOKB + m0) * CH);
    const char* Bg = (const char*)(k + (size_t)(z * NTOKB + n0) * CH);
    float acc[4][8][4] = {};
    main2<false>(Ag, Bg, (size_t)CH * 4, (size_t)CH * 4, (CH * 4) / 64, sm, acc);

    __nv_bfloat16* S = g_sh + (size_t)z * NTOKB * NTOKB;
    const int tid = threadIdx.x, lane = tid & 31, w = tid >> 5;
    const int wm0 = (w >> 2) * 64, wn0 = (w & 3) * 64;
    const int fg = lane >> 2, fq = lane & 3;

    float rsum[4][2] = {};
#pragma unroll
    for (int nt = 0; nt < 8; nt++) {
        const int col = n0 + wn0 + nt * 8 + 2 * fq;
#pragma unroll
        for (int mt = 0; mt < 4; mt++) {
            const int row = m0 + wm0 + mt * 16 + fg;
            float e0 = __expf(SCALE * acc[mt][nt][0]);
            float e1 = __expf(SCALE * acc[mt][nt][1]);
            float e2 = __expf(SCALE * acc[mt][nt][2]);
            float e3 = __expf(SCALE * acc[mt][nt][3]);
            *(__nv_bfloat162*)&S[(size_t)row * NTOKB + col]       = __floats2bfloat162_rn(e0, e1);
            *(__nv_bfloat162*)&S[(size_t)(row + 8) * NTOKB + col] = __floats2bfloat162_rn(e2, e3);
            rsum[mt][0] += e0 + e1;
            rsum[mt][1] += e2 + e3;
        }
    }
    const int rbase = z * NTOKB + m0 + wm0;
#pragma unroll
    for (int mt = 0; mt < 4; mt++) {
#pragma unroll
        for (int half = 0; half < 2; half++) {
            float vv = rsum[mt][half];
            vv += __shfl_xor_sync(0xffffffffu, vv, 1);
            vv += __shfl_xor_sync(0xffffffffu, vv, 2);
            if (fq == 0)
                atomicAdd(&g_rowsum[rbase + mt * 16 + fg + 8 * half], vv);
        }
    }
}

// ---------------- AV-gemm (bf16): O = (P @ V) / rowsum ----------------------
__global__ __launch_bounds__(256) void gemm_av(float* __restrict__ o)
{
    extern __shared__ char dynsm[];
    SM2* sm = (SM2*)dynsm;
    const int m0 = blockIdx.y * 128, n0 = blockIdx.x * 256, z = blockIdx.z;
    const char* Ag = (const char*)(g_sh + (size_t)z * NTOKB * NTOKB + (size_t)m0 * NTOKB);
    const char* Bg = (const char*)(g_vt + (size_t)z * CH * NTOKB + (size_t)n0 * NTOKB);
    float acc[4][8][4] = {};
    main2<true>(Ag, Bg, (size_t)NTOKB * 2, (size_t)NTOKB * 2, (NTOKB * 2) / 64, sm, acc);

    float* O = o + (size_t)z * NTOKB * CH;
    const int tid = threadIdx.x, lane = tid & 31, w = tid >> 5;
    const int wm0 = (w >> 2) * 64, wn0 = (w & 3) * 64;
    const int fg = lane >> 2, fq = lane & 3;

    const int rbase = z * NTOKB + m0 + wm0;
    float inv[4][2];
#pragma unroll
    for (int mt = 0; mt < 4; mt++) {
        inv[mt][0] = 1.f / g_rowsum[rbase + mt * 16 + fg];
        inv[mt][1] = 1.f / g_rowsum[rbase + mt * 16 + fg + 8];
    }
#pragma unroll
    for (int nt = 0; nt < 8; nt++) {
        const int col = n0 + wn0 + nt * 8 + 2 * fq;
#pragma unroll
        for (int mt = 0; mt < 4; mt++) {
            const int row = m0 + wm0 + mt * 16 + fg;
            float2 v0 = { acc[mt][nt][0] * inv[mt][0], acc[mt][nt][1] * inv[mt][0] };
            float2 v1 = { acc[mt][nt][2] * inv[mt][1], acc[mt][nt][3] * inv[mt][1] };
            *(float2*)&O[(size_t)row * CH + col]       = v0;
            *(float2*)&O[(size_t)(row + 8) * CH + col] = v1;
        }
    }
}

// ---------------- out-proj (tf32, big tile) + residual + transpose ----------
__global__ __launch_bounds__(256) void gemm_out_k(
    const float* __restrict__ o, const float* __restrict__ wo,
    const float* __restrict__ bo, const float* __restrict__ x, float* __restrict__ out)
{
    extern __shared__ char dynsm[];
    SM2* sm = (SM2*)dynsm;
    const int m0 = blockIdx.y * 128, n0 = blockIdx.x * 256;
    float acc[4][8][4] = {};
    main2<false>((const char*)(o + (size_t)m0 * CH), (const char*)(wo + (size_t)n0 * CH),
                 (size_t)CH * 4, (size_t)CH * 4, (CH * 4) / 64, sm, acc);

    const int tid = threadIdx.x, lane = tid & 31, w = tid >> 5;
    const int wm0 = (w >> 2) * 64, wn0 = (w & 3) * 64;
    const int fg = lane >> 2, fq = lane & 3;
#pragma unroll
    for (int nt = 0; nt < 8; nt++) {
        const int col = n0 + wn0 + nt * 8 + 2 * fq;
        const float b0 = bo[col];
        const float b1 = bo[col + 1];
#pragma unroll
        for (int mt = 0; mt < 4; mt++) {
#pragma unroll
            for (int half = 0; half < 2; half++) {
                const int row = m0 + wm0 + mt * 16 + fg + 8 * half;  // global token
                const int b = row >> 12;
                const int n = row & (NTOKB - 1);
                const size_t i0 = ((size_t)(b * CH + col)) * NTOKB + n;
                const size_t i1 = i0 + NTOKB;
                out[i0] = acc[mt][nt][2 * half + 0] + b0 + x[i0];
                out[i1] = acc[mt][nt][2 * half + 1] + b1 + x[i1];
            }
        }
    }
}

// ---------------- V transpose + convert to bf16 [B][C][N] -------------------
__global__ __launch_bounds__(256) void tv_kernel(const float* __restrict__ v)
{
    __shared__ float tile[32][33];
    const int b  = blockIdx.z;
    const int tx = threadIdx.x & 31, ty = threadIdx.x >> 5;   // 32 x 8
    const int ch0 = blockIdx.x * 32, tk0 = blockIdx.y * 32;
#pragma unroll
    for (int i = 0; i < 32; i += 8)
        tile[ty + i][tx] = v[((size_t)(b * NTOKB + tk0 + ty + i)) * CH + ch0 + tx];
    __syncthreads();
#pragma unroll
    for (int i = 0; i < 32; i += 8)
        g_vt[((size_t)(b * CH + ch0 + ty + i)) * NTOKB + tk0 + tx] =
            __float2bfloat16(tile[tx][ty + i]);
}

// ---------------- zero rowsum ------------------------------------------------
__global__ void zero_rowsum_kernel() {
    g_rowsum[blockIdx.x * 256 + threadIdx.x] = 0.f;
}

// ---------------- GroupNorm + coalesced transpose to [B, N, C] --------------
__global__ __launch_bounds__(512) void gn_kernel(
    const float* __restrict__ x, const float* __restrict__ gw,
    const float* __restrict__ gb)
{
    const int b = blockIdx.x >> 5;
    const int g = blockIdx.x & 31;
    const float* xp = x + ((size_t)(b * CH + g * CPG)) * NTOKB;

    float s = 0.f, ss = 0.f;
    const float4* xp4 = (const float4*)xp;
    for (int i = threadIdx.x; i < CPG * NTOKB / 4; i += 512) {
        float4 vv = xp4[i];
        s  += vv.x + vv.y + vv.z + vv.w;
        ss += vv.x * vv.x + vv.y * vv.y + vv.z * vv.z + vv.w * vv.w;
    }
    __shared__ float rs[16], rss[16], bc[2];
#pragma unroll
    for (int o = 16; o > 0; o >>= 1) {
        s  += __shfl_xor_sync(0xffffffffu, s, o);
        ss += __shfl_xor_sync(0xffffffffu, ss, o);
    }
    if ((threadIdx.x & 31) == 0) { rs[threadIdx.x >> 5] = s; rss[threadIdx.x >> 5] = ss; }
    __syncthreads();
    if (threadIdx.x < 32) {
        s  = (threadIdx.x < 16) ? rs[threadIdx.x]  : 0.f;
        ss = (threadIdx.x < 16) ? rss[threadIdx.x] : 0.f;
#pragma unroll
        for (int o = 8; o > 0; o >>= 1) {
            s  += __shfl_xor_sync(0xffffffffu, s, o);
            ss += __shfl_xor_sync(0xffffffffu, ss, o);
        }
        if (threadIdx.x == 0) {
            const float NEL = (float)(CPG * NTOKB);
            float mean = s / NEL;
            float var  = ss / NEL - mean * mean;
            bc[0] = mean;
            bc[1] = rsqrtf(var + EPS);
        }
    }
    __syncthreads();
    __shared__ float sa[CPG], sb2[CPG];
    if (threadIdx.x < CPG) {
        float a = bc[1] * gw[g * CPG + threadIdx.x];
        sa[threadIdx.x]  = a;
        sb2[threadIdx.x] = gb[g * CPG + threadIdx.x] - bc[0] * a;
    }
    __syncthreads();

    __shared__ float tile[CPG][132];
    const int c  = threadIdx.x >> 5, seg = threadIdx.x & 31;
    const int nl = threadIdx.x >> 2, cq  = threadIdx.x & 3;
    for (int t0 = 0; t0 < NTOKB; t0 += 128) {
        float4 vv = *(const float4*)(xp + (size_t)c * NTOKB + t0 + seg * 4);
        const float a = sa[c], bb = sb2[c];
        tile[c][seg * 4 + 0] = vv.x * a + bb;
        tile[c][seg * 4 + 1] = vv.y * a + bb;
        tile[c][seg * 4 + 2] = vv.z * a + bb;
        tile[c][seg * 4 + 3] = vv.w * a + bb;
        __syncthreads();
        float4 wv;
        wv.x = tile[cq * 4 + 0][nl];
        wv.y = tile[cq * 4 + 1][nl];
        wv.z = tile[cq * 4 + 2][nl];
        wv.w = tile[cq * 4 + 3][nl];
        *(float4*)(g_t + ((size_t)(b * NTOKB + t0 + nl)) * CH + g * CPG + cq * 4) = wv;
        __syncthreads();
    }
}

// ---------------- launch ----------------------------------------------------
extern "C" void kernel_launch(void* const* d_in, const int* in_sizes, int n_in,
                              void* d_out, int out_size)
{
    const float* x  = (const float*)d_in[0];
    const float* gw = (const float*)d_in[1];
    const float* gb = (const float*)d_in[2];
    const float* wq = (const float*)d_in[3];
    const float* bq = (const float*)d_in[4];
    const float* wk = (const float*)d_in[5];
    const float* bk = (const float*)d_in[6];
    const float* wv = (const float*)d_in[7];
    const float* bv = (const float*)d_in[8];
    const float* wo = (const float*)d_in[9];
    const float* bo = (const float*)d_in[10];
    float* out = (float*)d_out;

    float *t, *q, *k, *v, *o;
    cudaGetSymbolAddress((void**)&t, g_t);
    cudaGetSymbolAddress((void**)&q, g_q);
    cudaGetSymbolAddress((void**)&k, g_k);
    cudaGetSymbolAddress((void**)&v, g_v);
    cudaGetSymbolAddress((void**)&o, g_o);

    const int bigBytes = (int)sizeof(SM2);   // 92,160
    cudaFuncSetAttribute(gemm_qkv,   cudaFuncAttributeMaxDynamicSharedMemorySize, bigBytes);
    cudaFuncSetAttribute(gemm_s,     cudaFuncAttributeMaxDynamicSharedMemorySize, bigBytes);
    cudaFuncSetAttribute(gemm_av,    cudaFuncAttributeMaxDynamicSharedMemorySize, bigBytes);
    cudaFuncSetAttribute(gemm_out_k, cudaFuncAttributeMaxDynamicSharedMemorySize, bigBytes);

    // 0) zero softmax denominators (graph replays re-run this)
    zero_rowsum_kernel<<<NTOK / 256, 256>>>();

    // 1) GroupNorm -> token layout g_t [B*N, C]
    gn_kernel<<<BATCH * NGROUP, 512>>>(x, gw, gb);

    // 2) fused Q/K/V projections (tf32, 128x256)
    gemm_qkv<<<dim3(CH / 256, NTOK / 128, 3), 256, bigBytes>>>(t, wq, bq, q, wk, bk, k, wv, bv, v);

    // 2b) V -> V^T bf16
    tv_kernel<<<dim3(CH / 32, NTOKB / 32, BATCH), 256>>>(v);

    // 3) S = exp(scale * Q K^T) -> bf16 (tf32, 128x256)
    gemm_s<<<dim3(NTOKB / 256, NTOKB / 128, BATCH), 256, bigBytes>>>(q, k);

    // 4) O = (P V) / rowsum  (bf16, 128x256)
    gemm_av<<<dim3(CH / 256, NTOKB / 128, BATCH), 256, bigBytes>>>(o);

    // 5) out = O wo^T + bo, transpose to [B,C,H,W], + residual (tf32, 128x256)
    gemm_out_k<<<dim3(CH / 256, NTOK / 128, 1), 256, bigBytes>>>(o, wo, bo, x, out);
}

// round 17
// speedup vs baseline: 1.2488x; 1.2488x over previous
#include <cuda_runtime.h>
#include <cuda_bf16.h>
#include <cstdint>

#define BATCH  2
#define CH     512
#define NTOKB  4096              // tokens per batch (H*W)
#define NTOK   (BATCH * NTOKB)   // 8192
#define NGROUP 32
#define CPG    (CH / NGROUP)     // 16
#define EPS    1e-5f
#define SCALE  0.04419417382415922f   // 1/sqrt(512)

// ---------------- scratch (device globals; no allocations allowed) ----------
__device__ float g_t[(size_t)NTOK * CH];                 // normalized tokens [B*N, C]
__device__ __nv_bfloat16 g_qh[(size_t)NTOK * CH];        // Q bf16 [B*N, C]
__device__ __nv_bfloat16 g_kh[(size_t)NTOK * CH];        // K bf16 [B*N, C]
__device__ float g_v[(size_t)NTOK * CH];
__device__ float g_o[(size_t)NTOK * CH];
__device__ __nv_bfloat16 g_sh[(size_t)BATCH * NTOKB * NTOKB];  // exp(scores), bf16, 64 MB
__device__ __nv_bfloat16 g_vt[(size_t)BATCH * CH * NTOKB];     // V^T bf16 [B][C][N]
__device__ float g_rowsum[NTOK];                          // softmax denominators

// ---------------- primitives ------------------------------------------------
__device__ __forceinline__ void mma_tf32(float* d, const unsigned* a, const unsigned* b) {
    asm volatile(
        "mma.sync.aligned.m16n8k8.row.col.f32.tf32.tf32.f32 "
        "{%0,%1,%2,%3}, {%4,%5,%6,%7}, {%8,%9}, {%0,%1,%2,%3};\n"
        : "+f"(d[0]), "+f"(d[1]), "+f"(d[2]), "+f"(d[3])
        : "r"(a[0]), "r"(a[1]), "r"(a[2]), "r"(a[3]), "r"(b[0]), "r"(b[1]));
}
__device__ __forceinline__ void mma_bf16(float* d, const unsigned* a, const unsigned* b) {
    asm volatile(
        "mma.sync.aligned.m16n8k16.row.col.f32.bf16.bf16.f32 "
        "{%0,%1,%2,%3}, {%4,%5,%6,%7}, {%8,%9}, {%0,%1,%2,%3};\n"
        : "+f"(d[0]), "+f"(d[1]), "+f"(d[2]), "+f"(d[3])
        : "r"(a[0]), "r"(a[1]), "r"(a[2]), "r"(a[3]), "r"(b[0]), "r"(b[1]));
}

__device__ __forceinline__ unsigned smem_u32(const void* p) {
    return (unsigned)__cvta_generic_to_shared(p);
}
#define CP16(dst, src) asm volatile("cp.async.cg.shared.global [%0], [%1], 16;" :: "r"(dst), "l"(src))
#define CPCOMMIT()     asm volatile("cp.async.commit_group;")
#define CPWAIT1()      asm volatile("cp.async.wait_group 1;")

// ============================================================================
// Unified big-tile mainloop: block 128x256, 256 thr = 8 warps (2m x 4n),
// warp tile 64x64 -> 4x8 fragments.  k-chunk = 64 bytes per row
// (16 fp32 for tf32 / 32 bf16 for bf16) -> 2 mma k-steps per chunk.
// pitch 20 b32, conflict-free fragment LDS; ~1.0 LDS.32 per mma.
// ============================================================================
#define P2 20
struct SM2 { unsigned A[3][128][P2]; unsigned B[3][256][P2]; };   // 92,160 B

__device__ __forceinline__ void load2_A(unsigned (*dst)[P2], const char* src,
                                        size_t ld, int tid) {
#pragma unroll
    for (int i = 0; i < 2; i++) {
        int c = i * 256 + tid;
        int r = c >> 2, s = c & 3;
        CP16(smem_u32(&dst[r][s * 4]), src + (size_t)r * ld + s * 16);
    }
}
__device__ __forceinline__ void load2_B(unsigned (*dst)[P2], const char* src,
                                        size_t ld, int tid) {
#pragma unroll
    for (int i = 0; i < 4; i++) {
        int c = i * 256 + tid;
        int r = c >> 2, s = c & 3;
        CP16(smem_u32(&dst[r][s * 4]), src + (size_t)r * ld + s * 16);
    }
}

template<bool BF16>
__device__ __forceinline__ void main2(const char* Ag, const char* Bg,
                                      size_t lda, size_t ldb, int NK,
                                      SM2* sm, float acc[4][8][4])
{
    const int tid = threadIdx.x;
    const int lane = tid & 31, w = tid >> 5;
    const int wm0 = (w >> 2) * 64, wn0 = (w & 3) * 64;
    const int fg = lane >> 2, fq = lane & 3;

    load2_A(sm->A[0], Ag, lda, tid);
    load2_B(sm->B[0], Bg, ldb, tid);
    CPCOMMIT();
    load2_A(sm->A[1], Ag + 64, lda, tid);
    load2_B(sm->B[1], Bg + 64, ldb, tid);
    CPCOMMIT();

    int cur = 0, nxt = 2;
    for (int it = 0; it < NK; ++it) {
        CPWAIT1();
        __syncthreads();
        if (it + 2 < NK) {
            load2_A(sm->A[nxt], Ag + (size_t)(it + 2) * 64, lda, tid);
            load2_B(sm->B[nxt], Bg + (size_t)(it + 2) * 64, ldb, tid);
        }
        CPCOMMIT();

        const unsigned (*As)[P2] = sm->A[cur];
        const unsigned (*Bs)[P2] = sm->B[cur];
#pragma unroll
        for (int ks = 0; ks < 2; ks++) {
            const int c0 = ks * 8 + fq;           // b32 column of first frag reg
            unsigned bf[8][2];
#pragma unroll
            for (int nt = 0; nt < 8; nt++) {
                const int bn = wn0 + nt * 8 + fg;
                bf[nt][0] = Bs[bn][c0];
                bf[nt][1] = Bs[bn][c0 + 4];
            }
#pragma unroll
            for (int mt = 0; mt < 4; mt++) {
                unsigned af[4];
                const int am = wm0 + mt * 16 + fg;
                af[0] = As[am][c0];     af[1] = As[am + 8][c0];
                af[2] = As[am][c0 + 4]; af[3] = As[am + 8][c0 + 4];
#pragma unroll
                for (int nt = 0; nt < 8; nt++) {
                    if (BF16) mma_bf16(acc[mt][nt], af, bf[nt]);
                    else      mma_tf32(acc[mt][nt], af, bf[nt]);
                }
            }
        }
        cur = (cur == 2) ? 0 : cur + 1;
        nxt = (nxt == 2) ? 0 : nxt + 1;
    }
}

// ---------------- fused Q/K/V projection (tf32, big tile) -------------------
// z=0 -> Q bf16, z=1 -> K bf16, z=2 -> V fp32
__global__ __launch_bounds__(256) void gemm_qkv(
    const float* __restrict__ t,
    const float* __restrict__ wq, const float* __restrict__ bq,
    const float* __restrict__ wk, const float* __restrict__ bk,
    const float* __restrict__ wv, const float* __restrict__ bv)
{
    extern __shared__ char dynsm[];
    SM2* sm = (SM2*)dynsm;
    const int z = blockIdx.z;
    const float* W  = z == 0 ? wq : z == 1 ? wk : wv;
    const float* bs = z == 0 ? bq : z == 1 ? bk : bv;
    const int m0 = blockIdx.y * 128, n0 = blockIdx.x * 256;

    float acc[4][8][4] = {};
    main2<false>((const char*)(t + (size_t)m0 * CH), (const char*)(W + (size_t)n0 * CH),
                 (size_t)CH * 4, (size_t)CH * 4, (CH * 4) / 64, sm, acc);

    const int tid = threadIdx.x, lane = tid & 31, w = tid >> 5;
    const int wm0 = (w >> 2) * 64, wn0 = (w & 3) * 64;
    const int fg = lane >> 2, fq = lane & 3;
    __nv_bfloat16* H = (z == 0) ? g_qh : g_kh;
#pragma unroll
    for (int nt = 0; nt < 8; nt++) {
        const int col = n0 + wn0 + nt * 8 + 2 * fq;
        const float b0 = bs[col];
        const float b1 = bs[col + 1];
#pragma unroll
        for (int mt = 0; mt < 4; mt++) {
            const int row = m0 + wm0 + mt * 16 + fg;
            if (z < 2) {
                *(__nv_bfloat162*)&H[(size_t)row * CH + col] =
                    __floats2bfloat162_rn(acc[mt][nt][0] + b0, acc[mt][nt][1] + b1);
                *(__nv_bfloat162*)&H[(size_t)(row + 8) * CH + col] =
                    __floats2bfloat162_rn(acc[mt][nt][2] + b0, acc[mt][nt][3] + b1);
            } else {
                float2 v0 = { acc[mt][nt][0] + b0, acc[mt][nt][1] + b1 };
                float2 v1 = { acc[mt][nt][2] + b0, acc[mt][nt][3] + b1 };
                *(float2*)&g_v[(size_t)row * CH + col]       = v0;
                *(float2*)&g_v[(size_t)(row + 8) * CH + col] = v1;
            }
        }
    }
}

// ---------------- S-gemm (bf16): S = exp(scale * Q K^T) -> bf16 + rowsum ----
__global__ __launch_bounds__(256) void gemm_s()
{
    extern __shared__ char dynsm[];
    SM2* sm = (SM2*)dynsm;
    const int m0 = blockIdx.y * 128, n0 = blockIdx.x * 256, z = blockIdx.z;
    const char* Ag = (const char*)(g_qh + (size_t)(z * NTOKB + m0) * CH);
    const char* Bg = (const char*)(g_kh + (size_t)(z * NTOKB + n0) * CH);
    float acc[4][8][4] = {};
    main2<true>(Ag, Bg, (size_t)CH * 2, (size_t)CH * 2, (CH * 2) / 64, sm, acc);

    __nv_bfloat16* S = g_sh + (size_t)z * NTOKB * NTOKB;
    const int tid = threadIdx.x, lane = tid & 31, w = tid >> 5;
    const int wm0 = (w >> 2) * 64, wn0 = (w & 3) * 64;
    const int fg = lane >> 2, fq = lane & 3;

    float rsum[4][2] = {};
#pragma unroll
    for (int nt = 0; nt < 8; nt++) {
        const int col = n0 + wn0 + nt * 8 + 2 * fq;
#pragma unroll
        for (int mt = 0; mt < 4; mt++) {
            const int row = m0 + wm0 + mt * 16 + fg;
            float e0 = __expf(SCALE * acc[mt][nt][0]);
            float e1 = __expf(SCALE * acc[mt][nt][1]);
            float e2 = __expf(SCALE * acc[mt][nt][2]);
            float e3 = __expf(SCALE * acc[mt][nt][3]);
            *(__nv_bfloat162*)&S[(size_t)row * NTOKB + col]       = __floats2bfloat162_rn(e0, e1);
            *(__nv_bfloat162*)&S[(size_t)(row + 8) * NTOKB + col] = __floats2bfloat162_rn(e2, e3);
            rsum[mt][0] += e0 + e1;
            rsum[mt][1] += e2 + e3;
        }
    }
    const int rbase = z * NTOKB + m0 + wm0;
#pragma unroll
    for (int mt = 0; mt < 4; mt++) {
#pragma unroll
        for (int half = 0; half < 2; half++) {
            float vv = rsum[mt][half];
            vv += __shfl_xor_sync(0xffffffffu, vv, 1);
            vv += __shfl_xor_sync(0xffffffffu, vv, 2);
            if (fq == 0)
                atomicAdd(&g_rowsum[rbase + mt * 16 + fg + 8 * half], vv);
        }
    }
}

// ---------------- AV-gemm (bf16): O = (P @ V) / rowsum ----------------------
__global__ __launch_bounds__(256) void gemm_av(float* __restrict__ o)
{
    extern __shared__ char dynsm[];
    SM2* sm = (SM2*)dynsm;
    const int m0 = blockIdx.y * 128, n0 = blockIdx.x * 256, z = blockIdx.z;
    const char* Ag = (const char*)(g_sh + (size_t)z * NTOKB * NTOKB + (size_t)m0 * NTOKB);
    const char* Bg = (const char*)(g_vt + (size_t)z * CH * NTOKB + (size_t)n0 * NTOKB);
    float acc[4][8][4] = {};
    main2<true>(Ag, Bg, (size_t)NTOKB * 2, (size_t)NTOKB * 2, (NTOKB * 2) / 64, sm, acc);

    float* O = o + (size_t)z * NTOKB * CH;
    const int tid = threadIdx.x, lane = tid & 31, w = tid >> 5;
    const int wm0 = (w >> 2) * 64, wn0 = (w & 3) * 64;
    const int fg = lane >> 2, fq = lane & 3;

    const int rbase = z * NTOKB + m0 + wm0;
    float inv[4][2];
#pragma unroll
    for (int mt = 0; mt < 4; mt++) {
        inv[mt][0] = 1.f / g_rowsum[rbase + mt * 16 + fg];
        inv[mt][1] = 1.f / g_rowsum[rbase + mt * 16 + fg + 8];
    }
#pragma unroll
    for (int nt = 0; nt < 8; nt++) {
        const int col = n0 + wn0 + nt * 8 + 2 * fq;
#pragma unroll
        for (int mt = 0; mt < 4; mt++) {
            const int row = m0 + wm0 + mt * 16 + fg;
            float2 v0 = { acc[mt][nt][0] * inv[mt][0], acc[mt][nt][1] * inv[mt][0] };
            float2 v1 = { acc[mt][nt][2] * inv[mt][1], acc[mt][nt][3] * inv[mt][1] };
            *(float2*)&O[(size_t)row * CH + col]       = v0;
            *(float2*)&O[(size_t)(row + 8) * CH + col] = v1;
        }
    }
}

// ---------------- out-proj (tf32, big tile) + residual + transpose ----------
__global__ __launch_bounds__(256) void gemm_out_k(
    const float* __restrict__ o, const float* __restrict__ wo,
    const float* __restrict__ bo, const float* __restrict__ x, float* __restrict__ out)
{
    extern __shared__ char dynsm[];
    SM2* sm = (SM2*)dynsm;
    const int m0 = blockIdx.y * 128, n0 = blockIdx.x * 256;
    float acc[4][8][4] = {};
    main2<false>((const char*)(o + (size_t)m0 * CH), (const char*)(wo + (size_t)n0 * CH),
                 (size_t)CH * 4, (size_t)CH * 4, (CH * 4) / 64, sm, acc);

    const int tid = threadIdx.x, lane = tid & 31, w = tid >> 5;
    const int wm0 = (w >> 2) * 64, wn0 = (w & 3) * 64;
    const int fg = lane >> 2, fq = lane & 3;
#pragma unroll
    for (int nt = 0; nt < 8; nt++) {
        const int col = n0 + wn0 + nt * 8 + 2 * fq;
        const float b0 = bo[col];
        const float b1 = bo[col + 1];
#pragma unroll
        for (int mt = 0; mt < 4; mt++) {
#pragma unroll
            for (int half = 0; half < 2; half++) {
                const int row = m0 + wm0 + mt * 16 + fg + 8 * half;  // global token
                const int b = row >> 12;
                const int n = row & (NTOKB - 1);
                const size_t i0 = ((size_t)(b * CH + col)) * NTOKB + n;
                const size_t i1 = i0 + NTOKB;
                out[i0] = acc[mt][nt][2 * half + 0] + b0 + x[i0];
                out[i1] = acc[mt][nt][2 * half + 1] + b1 + x[i1];
            }
        }
    }
}

// ---------------- V transpose + convert to bf16 [B][C][N] -------------------
__global__ __launch_bounds__(256) void tv_kernel(const float* __restrict__ v)
{
    __shared__ float tile[32][33];
    const int b  = blockIdx.z;
    const int tx = threadIdx.x & 31, ty = threadIdx.x >> 5;   // 32 x 8
    const int ch0 = blockIdx.x * 32, tk0 = blockIdx.y * 32;
#pragma unroll
    for (int i = 0; i < 32; i += 8)
        tile[ty + i][tx] = v[((size_t)(b * NTOKB + tk0 + ty + i)) * CH + ch0 + tx];
    __syncthreads();
#pragma unroll
    for (int i = 0; i < 32; i += 8)
        g_vt[((size_t)(b * CH + ch0 + ty + i)) * NTOKB + tk0 + tx] =
            __float2bfloat16(tile[tx][ty + i]);
}

// ---------------- zero rowsum ------------------------------------------------
__global__ void zero_rowsum_kernel() {
    g_rowsum[blockIdx.x * 256 + threadIdx.x] = 0.f;
}

// ---------------- GroupNorm + coalesced transpose to [B, N, C] --------------
__global__ __launch_bounds__(512) void gn_kernel(
    const float* __restrict__ x, const float* __restrict__ gw,
    const float* __restrict__ gb)
{
    const int b = blockIdx.x >> 5;
    const int g = blockIdx.x & 31;
    const float* xp = x + ((size_t)(b * CH + g * CPG)) * NTOKB;

    float s = 0.f, ss = 0.f;
    const float4* xp4 = (const float4*)xp;
    for (int i = threadIdx.x; i < CPG * NTOKB / 4; i += 512) {
        float4 vv = xp4[i];
        s  += vv.x + vv.y + vv.z + vv.w;
        ss += vv.x * vv.x + vv.y * vv.y + vv.z * vv.z + vv.w * vv.w;
    }
    __shared__ float rs[16], rss[16], bc[2];
#pragma unroll
    for (int o = 16; o > 0; o >>= 1) {
        s  += __shfl_xor_sync(0xffffffffu, s, o);
        ss += __shfl_xor_sync(0xffffffffu, ss, o);
    }
    if ((threadIdx.x & 31) == 0) { rs[threadIdx.x >> 5] = s; rss[threadIdx.x >> 5] = ss; }
    __syncthreads();
    if (threadIdx.x < 32) {
        s  = (threadIdx.x < 16) ? rs[threadIdx.x]  : 0.f;
        ss = (threadIdx.x < 16) ? rss[threadIdx.x] : 0.f;
#pragma unroll
        for (int o = 8; o > 0; o >>= 1) {
            s  += __shfl_xor_sync(0xffffffffu, s, o);
            ss += __shfl_xor_sync(0xffffffffu, ss, o);
        }
        if (threadIdx.x == 0) {
            const float NEL = (float)(CPG * NTOKB);
            float mean = s / NEL;
            float var  = ss / NEL - mean * mean;
            bc[0] = mean;
            bc[1] = rsqrtf(var + EPS);
        }
    }
    __syncthreads();
    __shared__ float sa[CPG], sb2[CPG];
    if (threadIdx.x < CPG) {
        float a = bc[1] * gw[g * CPG + threadIdx.x];
        sa[threadIdx.x]  = a;
        sb2[threadIdx.x] = gb[g * CPG + threadIdx.x] - bc[0] * a;
    }
    __syncthreads();

    __shared__ float tile[CPG][132];
    const int c  = threadIdx.x >> 5, seg = threadIdx.x & 31;
    const int nl = threadIdx.x >> 2, cq  = threadIdx.x & 3;
    for (int t0 = 0; t0 < NTOKB; t0 += 128) {
        float4 vv = *(const float4*)(xp + (size_t)c * NTOKB + t0 + seg * 4);
        const float a = sa[c], bb = sb2[c];
        tile[c][seg * 4 + 0] = vv.x * a + bb;
        tile[c][seg * 4 + 1] = vv.y * a + bb;
        tile[c][seg * 4 + 2] = vv.z * a + bb;
        tile[c][seg * 4 + 3] = vv.w * a + bb;
        __syncthreads();
        float4 wv;
        wv.x = tile[cq * 4 + 0][nl];
        wv.y = tile[cq * 4 + 1][nl];
        wv.z = tile[cq * 4 + 2][nl];
        wv.w = tile[cq * 4 + 3][nl];
        *(float4*)(g_t + ((size_t)(b * NTOKB + t0 + nl)) * CH + g * CPG + cq * 4) = wv;
        __syncthreads();
    }
}

// ---------------- launch ----------------------------------------------------
extern "C" void kernel_launch(void* const* d_in, const int* in_sizes, int n_in,
                              void* d_out, int out_size)
{
    const float* x  = (const float*)d_in[0];
    const float* gw = (const float*)d_in[1];
    const float* gb = (const float*)d_in[2];
    const float* wq = (const float*)d_in[3];
    const float* bq = (const float*)d_in[4];
    const float* wk = (const float*)d_in[5];
    const float* bk = (const float*)d_in[6];
    const float* wv = (const float*)d_in[7];
    const float* bv = (const float*)d_in[8];
    const float* wo = (const float*)d_in[9];
    const float* bo = (const float*)d_in[10];
    float* out = (float*)d_out;

    float *t, *v, *o;
    cudaGetSymbolAddress((void**)&t, g_t);
    cudaGetSymbolAddress((void**)&v, g_v);
    cudaGetSymbolAddress((void**)&o, g_o);

    const int bigBytes = (int)sizeof(SM2);   // 92,160
    cudaFuncSetAttribute(gemm_qkv,   cudaFuncAttributeMaxDynamicSharedMemorySize, bigBytes);
    cudaFuncSetAttribute(gemm_s,     cudaFuncAttributeMaxDynamicSharedMemorySize, bigBytes);
    cudaFuncSetAttribute(gemm_av,    cudaFuncAttributeMaxDynamicSharedMemorySize, bigBytes);
    cudaFuncSetAttribute(gemm_out_k, cudaFuncAttributeMaxDynamicSharedMemorySize, bigBytes);

    // 0) zero softmax denominators (graph replays re-run this)
    zero_rowsum_kernel<<<NTOK / 256, 256>>>();

    // 1) GroupNorm -> token layout g_t [B*N, C]
    gn_kernel<<<BATCH * NGROUP, 512>>>(x, gw, gb);

    // 2) fused Q/K/V projections (tf32 main, bf16 Q/K outputs)
    gemm_qkv<<<dim3(CH / 256, NTOK / 128, 3), 256, bigBytes>>>(t, wq, bq, wk, bk, wv, bv);

    // 2b) V -> V^T bf16
    tv_kernel<<<dim3(CH / 32, NTOKB / 32, BATCH), 256>>>(v);

    // 3) S = exp(scale * Q K^T) -> bf16 (bf16 gemm, 128x256)
    gemm_s<<<dim3(NTOKB / 256, NTOKB / 128, BATCH), 256, bigBytes>>>();

    // 4) O = (P V) / rowsum  (bf16, 128x256)
    gemm_av<<<dim3(CH / 256, NTOKB / 128, BATCH), 256, bigBytes>>>(o);

    // 5) out = O wo^T + bo, transpose to [B,C,H,W], + residual (tf32, 128x256)
    gemm_out_k<<<dim3(CH / 256, NTOK / 128, 1), 256, bigBytes>>>(o, wo, bo, x, out);
}